// round 1
// baseline (speedup 1.0000x reference)
#include <cuda_runtime.h>

#define BB 2048
#define TT 512
#define VOCAB 4
#define EE 64
#define HH 128
#define G3 384        // 3*H
#define MTILE 16
#define NBLK (BB/MTILE)   // 128 CTAs
#define NTHR 384

// ---- scratch (no allocs allowed) ----
__device__ float         g_gi[VOCAB * G3];     // gi table: x-side projection + b_ih
__device__ unsigned char g_tok[TT * BB];       // tokens, [t][b] layout, uint8
__device__ int           g_is64;               // dtype of x

// ---- smem layout (bytes) ----
#define OFF_W    0                      // 384*128 f32 swizzled      = 196608
#define OFF_H    196608                 // 16*128 f32 h tile         =   8192
#define OFF_RZ   204800                 // 2*16*128 f32 r/z          =  16384
#define OFF_GI   221184                 // 4*384 f32                 =   6144
#define OFF_TOK  227328                 // 2*16 uchar                =     32
#define SMEM_BYTES 227360

// Detect whether x buffer is int64 or int32: tokens are 0..3, so if int64 all
// odd int32 lanes (high words) are zero. P(all-zero for int32 data) = 4^-64.
__global__ void detect_kernel(const int* __restrict__ x32) {
    int all_zero = 1;
    for (int i = 1; i < 128; i += 2) all_zero &= (x32[i] == 0);
    g_is64 = all_zero;
}

// Repack tokens int64/int32 [B][T] -> uint8 [T][B]
__global__ void tok_kernel(const void* __restrict__ xraw) {
    int i = blockIdx.x * blockDim.x + threadIdx.x;
    if (i >= BB * TT) return;
    int b = i / TT, t = i % TT;
    int v;
    if (g_is64) v = (int)((const long long*)xraw)[i];
    else        v = ((const int*)xraw)[i];
    g_tok[t * BB + b] = (unsigned char)v;
}

// gi_table[v][g] = b_ih[g] + dot(W_ih[g,:], emb[v,:])
__global__ void gi_kernel(const float* __restrict__ W_ih,
                          const float* __restrict__ emb,
                          const float* __restrict__ b_ih) {
    int g = threadIdx.x;
    if (g >= G3) return;
    float bi = b_ih[g];
    for (int v = 0; v < VOCAB; ++v) {
        float s = bi;
#pragma unroll 8
        for (int e = 0; e < EE; ++e) s += W_ih[g * EE + e] * emb[v * EE + e];
        g_gi[v * G3 + g] = s;
    }
}

__device__ __forceinline__ float sigmoid_f(float x) {
    // 1/(1+exp(-x)); inf handled gracefully (1/(1+inf)=0)
    return 1.0f / (1.0f + __expf(-x));
}
__device__ __forceinline__ float tanh_f(float x) {
    float xc = fminf(fmaxf(x, -15.0f), 15.0f);  // avoid inf/inf NaN
    float e2 = __expf(-2.0f * xc);
    return (1.0f - e2) / (1.0f + e2);
}

extern __shared__ char smem[];

__global__ __launch_bounds__(NTHR, 1)
void gru_kernel(const float* __restrict__ W_hh, const float* __restrict__ b_hh,
                const float* __restrict__ W_fc, const float* __restrict__ b_fc,
                float* __restrict__ out) {
    float4*        W_s4  = (float4*)(smem + OFF_W);
    float4*        h_s4  = (float4*)(smem + OFF_H);
    float*         h_s   = (float*)(smem + OFF_H);
    float*         rz_s  = (float*)(smem + OFF_RZ);
    float*         gi_s  = (float*)(smem + OFF_GI);
    unsigned char* tok_s = (unsigned char*)(smem + OFF_TOK);

    const int g    = threadIdx.x;          // 0..383  (output gate-unit column)
    const int row0 = blockIdx.x * MTILE;   // first batch row of this CTA

    // --- init: W_hh into smem, XOR-swizzled on 16B chunks (conflict-free LDS.128)
    {
        const float4* Wg = (const float4*)(W_hh + g * HH);
        int sw = g & 7;
#pragma unroll 4
        for (int c = 0; c < 32; ++c) W_s4[g * 32 + (c ^ sw)] = Wg[c];
    }
    for (int i = g; i < VOCAB * G3; i += NTHR) gi_s[i] = g_gi[i];
    for (int i = g; i < MTILE * HH; i += NTHR) h_s[i] = 0.0f;
    if (g < MTILE) tok_s[g] = g_tok[0 * BB + row0 + g];
    const float bhh = b_hh[g];
    __syncthreads();

    const int     sw   = g & 7;
    const float4* Wrow = W_s4 + g * 32;

    for (int t = 0; t < TT; ++t) {
        // prefetch next step's tokens (latency hidden behind k-loop)
        unsigned char nt = 0;
        if (g < MTILE && t + 1 < TT) nt = g_tok[(t + 1) * BB + row0 + g];

        // ---- gh[m][g] = b_hh[g] + sum_k h[m][k] * W_hh[g][k] ----
        float acc[MTILE];
#pragma unroll
        for (int m = 0; m < MTILE; ++m) acc[m] = bhh;
#pragma unroll 4
        for (int c = 0; c < 32; ++c) {
            float4 w = Wrow[c ^ sw];
#pragma unroll
            for (int m = 0; m < MTILE; ++m) {
                float4 hv = h_s4[m * 32 + c];   // warp-broadcast
                acc[m] = fmaf(w.x, hv.x, acc[m]);
                acc[m] = fmaf(w.y, hv.y, acc[m]);
                acc[m] = fmaf(w.z, hv.z, acc[m]);
                acc[m] = fmaf(w.w, hv.w, acc[m]);
            }
        }

        const int cur = t & 1, nxt = cur ^ 1;

        if (g < 256) {
            // r gate (g<128) and z gate (128<=g<256)
            const int gate = g >> 7;
            const int j    = g & 127;
#pragma unroll
            for (int m = 0; m < MTILE; ++m) {
                int   v = tok_s[cur * MTILE + m];
                float x = gi_s[v * G3 + g] + acc[m];
                rz_s[gate * 2048 + m * HH + j] = sigmoid_f(x);
            }
            if (g < MTILE) tok_s[nxt * MTILE + g] = nt;
        }
        __syncthreads();
        if (g >= 256) {
            // n gate + h update;  n = tanh(gi_n + r * gh_n), gh_n includes b_hh
            const int j = g - 256;
#pragma unroll
            for (int m = 0; m < MTILE; ++m) {
                int   v    = tok_s[cur * MTILE + m];
                float r    = rz_s[m * HH + j];
                float z    = rz_s[2048 + m * HH + j];
                float n    = tanh_f(gi_s[v * G3 + g] + r * acc[m]);
                float hold = h_s[m * HH + j];
                h_s[m * HH + j] = (1.0f - z) * n + z * hold;
            }
        }
        __syncthreads();
    }

    // ---- logits = hT @ W_fc.T + b_fc ----
    if (g < MTILE * VOCAB) {
        int m = g >> 2, v = g & 3;
        float        sum = b_fc[v];
        const float* w   = W_fc + v * HH;
        const float* hr  = h_s + m * HH;
#pragma unroll 8
        for (int j = 0; j < HH; ++j) sum = fmaf(hr[j], w[j], sum);
        out[(row0 + m) * VOCAB + v] = sum;
    }
}

extern "C" void kernel_launch(void* const* d_in, const int* in_sizes, int n_in,
                              void* d_out, int out_size) {
    const void*  x    = d_in[0];                 // int64 or int32 tokens [B,T]
    const float* emb  = (const float*)d_in[1];   // [V,E]
    const float* W_ih = (const float*)d_in[2];   // [3H,E]
    const float* W_hh = (const float*)d_in[3];   // [3H,H]
    const float* b_ih = (const float*)d_in[4];   // [3H]
    const float* b_hh = (const float*)d_in[5];   // [3H]
    const float* W_fc = (const float*)d_in[6];   // [V,H]
    const float* b_fc = (const float*)d_in[7];   // [V]
    float* out = (float*)d_out;                  // [B,V]

    static int smem_set = 0;
    if (!smem_set) {
        cudaFuncSetAttribute(gru_kernel,
                             cudaFuncAttributeMaxDynamicSharedMemorySize,
                             SMEM_BYTES);
        smem_set = 1;
    }

    detect_kernel<<<1, 1>>>((const int*)x);
    tok_kernel<<<(BB * TT + 255) / 256, 256>>>(x);
    gi_kernel<<<1, G3>>>(W_ih, emb, b_ih);
    gru_kernel<<<NBLK, NTHR, SMEM_BYTES>>>(W_hh, b_hh, W_fc, b_fc, out);
}

// round 2
// speedup vs baseline: 1.3365x; 1.3365x over previous
#include <cuda_runtime.h>

#define BB 2048
#define TT 512
#define VOCAB 4
#define EE 64
#define HH 128
#define G3 384        // 3*H
#define MTILE 16
#define NBLK (BB/MTILE)   // 128 CTAs
#define NTHR 384

// ---- scratch (no allocs allowed) ----
__device__ float         g_gi[VOCAB * G3];
__device__ unsigned char g_tok[TT * BB];
__device__ int           g_is64;

// ---- smem layout (bytes) ----
#define OFF_W    0                      // 384*128 f32 swizzled      = 196608
#define OFF_H    196608                 // 16*128 f32 h tile         =   8192
#define OFF_RZ   204800                 // 2*16*128 f32 r/z          =  16384
#define OFF_GI   221184                 // 4*384 f32                 =   6144
#define OFF_TOK  227328                 // 2*16 uchar                =     32
#define SMEM_BYTES 227360

// packed fp32x2 FMA (Blackwell): d.lo = a.lo*b.lo + c.lo, same for hi.
__device__ __forceinline__ unsigned long long fma2(unsigned long long a,
                                                   unsigned long long b,
                                                   unsigned long long c) {
    unsigned long long d;
    asm("fma.rn.f32x2 %0, %1, %2, %3;" : "=l"(d) : "l"(a), "l"(b), "l"(c));
    return d;
}
__device__ __forceinline__ float reduce2(unsigned long long a) {
    unsigned int lo, hi;
    asm("mov.b64 {%0, %1}, %2;" : "=r"(lo), "=r"(hi) : "l"(a));
    return __uint_as_float(lo) + __uint_as_float(hi);
}

__global__ void detect_kernel(const int* __restrict__ x32) {
    int all_zero = 1;
    for (int i = 1; i < 128; i += 2) all_zero &= (x32[i] == 0);
    g_is64 = all_zero;
}

__global__ void tok_kernel(const void* __restrict__ xraw) {
    int i = blockIdx.x * blockDim.x + threadIdx.x;
    if (i >= BB * TT) return;
    int b = i / TT, t = i % TT;
    int v;
    if (g_is64) v = (int)((const long long*)xraw)[i];
    else        v = ((const int*)xraw)[i];
    g_tok[t * BB + b] = (unsigned char)v;
}

__global__ void gi_kernel(const float* __restrict__ W_ih,
                          const float* __restrict__ emb,
                          const float* __restrict__ b_ih) {
    int g = threadIdx.x;
    if (g >= G3) return;
    float bi = b_ih[g];
    for (int v = 0; v < VOCAB; ++v) {
        float s = bi;
#pragma unroll 8
        for (int e = 0; e < EE; ++e) s += W_ih[g * EE + e] * emb[v * EE + e];
        g_gi[v * G3 + g] = s;
    }
}

__device__ __forceinline__ float sigmoid_f(float x) {
    return 1.0f / (1.0f + __expf(-x));
}
__device__ __forceinline__ float tanh_f(float x) {
    float xc = fminf(fmaxf(x, -15.0f), 15.0f);
    float e2 = __expf(-2.0f * xc);
    return (1.0f - e2) / (1.0f + e2);
}

extern __shared__ char smem[];

__global__ __launch_bounds__(NTHR, 1)
void gru_kernel(const float* __restrict__ W_hh, const float* __restrict__ b_hh,
                const float* __restrict__ W_fc, const float* __restrict__ b_fc,
                float* __restrict__ out) {
    float4*        W_s4  = (float4*)(smem + OFF_W);
    float*         h_s   = (float*)(smem + OFF_H);
    float*         rz_s  = (float*)(smem + OFF_RZ);
    float*         gi_s  = (float*)(smem + OFF_GI);
    unsigned char* tok_s = (unsigned char*)(smem + OFF_TOK);

    const int tid  = threadIdx.x;          // 0..383
    const int mh   = tid / 192;            // m-half: rows 8*mh .. 8*mh+7
    const int col  = tid % 192;
    const int cA   = col;                  // column A (0..191): r or z gate
    const int cB   = col + 192;            // column B (192..383): z or n gate
    const int m0   = mh * 8;
    const int row0 = blockIdx.x * MTILE;

    // W_hh into smem, XOR-swizzled on 16B chunks (thread tid loads row tid)
    {
        const float4* Wg = (const float4*)(W_hh + tid * HH);
        int sw = tid & 7;
#pragma unroll 4
        for (int c = 0; c < 32; ++c) W_s4[tid * 32 + (c ^ sw)] = Wg[c];
    }
    for (int i = tid; i < VOCAB * G3; i += NTHR) gi_s[i] = g_gi[i];
    for (int i = tid; i < MTILE * HH; i += NTHR) h_s[i] = 0.0f;
    if (tid < MTILE) tok_s[tid] = g_tok[0 * BB + row0 + tid];

    // biases packed into the low f32x2 lane (hi lane starts at 0)
    const unsigned long long bAp = (unsigned long long)__float_as_uint(b_hh[cA]);
    const unsigned long long bBp = (unsigned long long)__float_as_uint(b_hh[cB]);
    __syncthreads();

    const int sw = cA & 7;                 // (cA+192)&7 == cA&7 since 192%8==0
    const ulonglong2* Wa = (const ulonglong2*)(W_s4 + cA * 32);
    const ulonglong2* Wb = (const ulonglong2*)(W_s4 + cB * 32);

    for (int t = 0; t < TT; ++t) {
        unsigned char nt = 0;
        if (tid < MTILE && t + 1 < TT) nt = g_tok[(t + 1) * BB + row0 + tid];

        // ---- gh = b_hh + h @ W_hh^T  (f32x2: lo=even-k partial, hi=odd-k) ----
        unsigned long long accA[8], accB[8];
#pragma unroll
        for (int m = 0; m < 8; ++m) { accA[m] = bAp; accB[m] = bBp; }
#pragma unroll 4
        for (int c = 0; c < 32; ++c) {
            ulonglong2 wa = Wa[c ^ sw];
            ulonglong2 wb = Wb[c ^ sw];
#pragma unroll
            for (int m = 0; m < 8; ++m) {
                ulonglong2 hv = ((const ulonglong2*)(h_s + (m0 + m) * HH))[c];
                accA[m] = fma2(hv.x, wa.x, accA[m]);
                accA[m] = fma2(hv.y, wa.y, accA[m]);
                accB[m] = fma2(hv.x, wb.x, accB[m]);
                accB[m] = fma2(hv.y, wb.y, accB[m]);
            }
        }
        float ghA[8], ghB[8];
#pragma unroll
        for (int m = 0; m < 8; ++m) { ghA[m] = reduce2(accA[m]); ghB[m] = reduce2(accB[m]); }

        const int cur = t & 1, nxt = cur ^ 1;

        // ---- phase 1: r/z sigmoids into rz_s (n-columns keep raw gh in regs) ----
        {
            // column A: r (cA<128) at rz[m*128+cA], else z at rz[2048+m*128+cA-128]
            float* dstA = (cA < 128) ? (rz_s + cA) : (rz_s + 2048 + (cA - 128));
#pragma unroll
            for (int m = 0; m < 8; ++m) {
                int mm = m0 + m;
                int v  = tok_s[cur * MTILE + mm];
                dstA[mm * HH] = sigmoid_f(gi_s[v * G3 + cA] + ghA[m]);
            }
            if (cB < 256) {  // column B is a z column
                float* dstB = rz_s + 2048 + (cB - 128);
#pragma unroll
                for (int m = 0; m < 8; ++m) {
                    int mm = m0 + m;
                    int v  = tok_s[cur * MTILE + mm];
                    dstB[mm * HH] = sigmoid_f(gi_s[v * G3 + cB] + ghB[m]);
                }
            }
        }
        __syncthreads();

        // ---- phase 2: n = tanh(gi_n + r*gh_n), h update (threads owning n cols) ----
        if (cB >= 256) {
            const int j = cB - 256;
#pragma unroll
            for (int m = 0; m < 8; ++m) {
                int   mm = m0 + m;
                int   v  = tok_s[cur * MTILE + mm];
                float r  = rz_s[mm * HH + j];
                float z  = rz_s[2048 + mm * HH + j];
                float n  = tanh_f(gi_s[v * G3 + 256 + j] + r * ghB[m]);
                float ho = h_s[mm * HH + j];
                h_s[mm * HH + j] = (1.0f - z) * n + z * ho;
            }
        } else if (tid < MTILE) {
            tok_s[nxt * MTILE + tid] = nt;   // idle threads stage next tokens
        }
        __syncthreads();
    }

    // ---- logits = hT @ W_fc.T + b_fc ----
    if (tid < MTILE * VOCAB) {
        int m = tid >> 2, v = tid & 3;
        float        sum = b_fc[v];
        const float* w   = W_fc + v * HH;
        const float* hr  = h_s + m * HH;
#pragma unroll 8
        for (int j = 0; j < HH; ++j) sum = fmaf(hr[j], w[j], sum);
        out[(row0 + m) * VOCAB + v] = sum;
    }
}

extern "C" void kernel_launch(void* const* d_in, const int* in_sizes, int n_in,
                              void* d_out, int out_size) {
    const void*  x    = d_in[0];
    const float* emb  = (const float*)d_in[1];
    const float* W_ih = (const float*)d_in[2];
    const float* W_hh = (const float*)d_in[3];
    const float* b_ih = (const float*)d_in[4];
    const float* b_hh = (const float*)d_in[5];
    const float* W_fc = (const float*)d_in[6];
    const float* b_fc = (const float*)d_in[7];
    float* out = (float*)d_out;

    static int smem_set = 0;
    if (!smem_set) {
        cudaFuncSetAttribute(gru_kernel,
                             cudaFuncAttributeMaxDynamicSharedMemorySize,
                             SMEM_BYTES);
        smem_set = 1;
    }

    detect_kernel<<<1, 1>>>((const int*)x);
    tok_kernel<<<(BB * TT + 255) / 256, 256>>>(x);
    gi_kernel<<<1, G3>>>(W_ih, emb, b_ih);
    gru_kernel<<<NBLK, NTHR, SMEM_BYTES>>>(W_hh, b_hh, W_fc, b_fc, out);
}

// round 4
// speedup vs baseline: 1.7650x; 1.3206x over previous
#include <cuda_runtime.h>

#define BB 2048
#define TT 512
#define VOCAB 4
#define EE 64
#define HH 128
#define G3 384        // 3*H
#define MTILE 16
#define NBLK (BB/MTILE)   // 128 CTAs
#define NTHR 256          // 128 units x 2 m-groups

// ---- scratch (no allocs allowed) ----
__device__ float         g_gi[VOCAB * G3];
__device__ unsigned char g_tok[TT * BB];
__device__ int           g_is64;

// ---- smem layout (bytes) ----
#define OFF_W    0                      // 384*128 f32 swizzled   = 196608
#define OFF_H0   196608                 // 16*128 f32 h buf 0     =   8192
#define OFF_H1   204800                 // 16*128 f32 h buf 1     =   8192
#define OFF_GI   212992                 // 4*384 f32              =   6144
#define OFF_TOK  219136                 // 2*16 uchar             =     32
#define SMEM_BYTES 219168

// packed fp32x2 FMA (Blackwell)
__device__ __forceinline__ unsigned long long fma2(unsigned long long a,
                                                   unsigned long long b,
                                                   unsigned long long c) {
    unsigned long long d;
    asm("fma.rn.f32x2 %0, %1, %2, %3;" : "=l"(d) : "l"(a), "l"(b), "l"(c));
    return d;
}
__device__ __forceinline__ float reduce2(unsigned long long a) {
    unsigned int lo, hi;
    asm("mov.b64 {%0, %1}, %2;" : "=r"(lo), "=r"(hi) : "l"(a));
    return __uint_as_float(lo) + __uint_as_float(hi);
}
__device__ __forceinline__ float tanh_fast(float x) {
    float y;
    asm("tanh.approx.f32 %0, %1;" : "=f"(y) : "f"(x));
    return y;
}
__device__ __forceinline__ float sigmoid_fast(float x) {
    return fmaf(tanh_fast(0.5f * x), 0.5f, 0.5f);
}

__global__ void detect_kernel(const int* __restrict__ x32) {
    int all_zero = 1;
    for (int i = 1; i < 128; i += 2) all_zero &= (x32[i] == 0);
    g_is64 = all_zero;
}

__global__ void tok_kernel(const void* __restrict__ xraw) {
    int i = blockIdx.x * blockDim.x + threadIdx.x;
    if (i >= BB * TT) return;
    int b = i / TT, t = i % TT;
    int v;
    if (g_is64) v = (int)((const long long*)xraw)[i];
    else        v = ((const int*)xraw)[i];
    g_tok[t * BB + b] = (unsigned char)v;
}

__global__ void gi_kernel(const float* __restrict__ W_ih,
                          const float* __restrict__ emb,
                          const float* __restrict__ b_ih) {
    int g = threadIdx.x;
    if (g >= G3) return;
    float bi = b_ih[g];
    for (int v = 0; v < VOCAB; ++v) {
        float s = bi;
#pragma unroll 8
        for (int e = 0; e < EE; ++e) s += W_ih[g * EE + e] * emb[v * EE + e];
        g_gi[v * G3 + g] = s;
    }
}

extern __shared__ char smem[];

__global__ __launch_bounds__(NTHR, 1)
void gru_kernel(const float* __restrict__ W_hh, const float* __restrict__ b_hh,
                const float* __restrict__ W_fc, const float* __restrict__ b_fc,
                float* __restrict__ out) {
    float*         h0_s  = (float*)(smem + OFF_H0);
    float*         h1_s  = (float*)(smem + OFF_H1);
    float*         gi_s  = (float*)(smem + OFF_GI);
    unsigned char* tok_s = (unsigned char*)(smem + OFF_TOK);

    const int tid  = threadIdx.x;     // 0..255
    const int j    = tid & 127;       // hidden unit
    const int mg   = tid >> 7;        // m-group: rows 8*mg..8*mg+7
    const int m0   = mg * 8;
    const int row0 = blockIdx.x * MTILE;

    // W_hh -> smem, XOR-swizzled on 16B granules (row r granule c at c^(r&7))
    {
        float4* W_s4 = (float4*)(smem + OFF_W);
        for (int r = tid; r < G3; r += NTHR) {
            const float4* Wg = (const float4*)(W_hh + r * HH);
            int sw = r & 7;
#pragma unroll 4
            for (int c = 0; c < 32; ++c) W_s4[r * 32 + (c ^ sw)] = Wg[c];
        }
    }
    for (int i = tid; i < VOCAB * G3; i += NTHR) gi_s[i] = g_gi[i];
    for (int i = tid; i < MTILE * HH; i += NTHR) h0_s[i] = 0.0f;
    if (tid < MTILE) tok_s[tid] = g_tok[0 * BB + row0 + tid];

    const unsigned long long bR = (unsigned long long)__float_as_uint(b_hh[j]);
    const unsigned long long bZ = (unsigned long long)__float_as_uint(b_hh[128 + j]);
    const unsigned long long bN = (unsigned long long)__float_as_uint(b_hh[256 + j]);
    __syncthreads();

    const int sw = j & 7;   // (j+128)&7 == (j+256)&7 == j&7
    const ulonglong2* Wr = (const ulonglong2*)(smem + OFF_W) + (j)       * 32;
    const ulonglong2* Wz = (const ulonglong2*)(smem + OFF_W) + (128 + j) * 32;
    const ulonglong2* Wn = (const ulonglong2*)(smem + OFF_W) + (256 + j) * 32;

    const float giRbase0 = 0.0f; (void)giRbase0;

    for (int t = 0; t < TT; ++t) {
        const int cur = t & 1;
        float* h_cur = cur ? h1_s : h0_s;
        float* h_nxt = cur ? h0_s : h1_s;
        const ulonglong2* hc2 = (const ulonglong2*)h_cur;

        // prefetch next tokens (latency hidden behind the GEMM)
        unsigned char nt = 0;
        if (tid < MTILE && t + 1 < TT) nt = g_tok[(t + 1) * BB + row0 + tid];

        // ---- gh = b_hh + h @ W_hh^T for all 3 gates of unit j, 8 rows ----
        unsigned long long aR[8], aZ[8], aN[8];
#pragma unroll
        for (int m = 0; m < 8; ++m) { aR[m] = bR; aZ[m] = bZ; aN[m] = bN; }
#pragma unroll 4
        for (int c = 0; c < 32; ++c) {
            ulonglong2 wr = Wr[c ^ sw];
            ulonglong2 wz = Wz[c ^ sw];
            ulonglong2 wn = Wn[c ^ sw];
#pragma unroll
            for (int m = 0; m < 8; ++m) {
                ulonglong2 hv = hc2[(m0 + m) * 32 + c];   // warp-broadcast
                aR[m] = fma2(hv.x, wr.x, aR[m]);
                aR[m] = fma2(hv.y, wr.y, aR[m]);
                aZ[m] = fma2(hv.x, wz.x, aZ[m]);
                aZ[m] = fma2(hv.y, wz.y, aZ[m]);
                aN[m] = fma2(hv.x, wn.x, aN[m]);
                aN[m] = fma2(hv.y, wn.y, aN[m]);
            }
        }

        // ---- gates + h update, all thread-local ----
#pragma unroll
        for (int m = 0; m < 8; ++m) {
            int   mm  = m0 + m;
            int   v   = tok_s[cur * MTILE + mm];
            const float* gv = gi_s + v * G3;
            float r   = sigmoid_fast(gv[j]       + reduce2(aR[m]));
            float z   = sigmoid_fast(gv[128 + j] + reduce2(aZ[m]));
            float n   = tanh_fast   (gv[256 + j] + r * reduce2(aN[m]));
            float ho  = h_cur[mm * HH + j];
            h_nxt[mm * HH + j] = fmaf(z, ho - n, n);   // (1-z)*n + z*ho
        }
        if (tid < MTILE) tok_s[(cur ^ 1) * MTILE + tid] = nt;
        __syncthreads();
    }

    // ---- logits = hT @ W_fc.T + b_fc  (final h is in buffer 0: TT even) ----
    if (tid < MTILE * VOCAB) {
        int m = tid >> 2, v = tid & 3;
        float        sum = b_fc[v];
        const float* w   = W_fc + v * HH;
        const float* hr  = h0_s + m * HH;
#pragma unroll 8
        for (int k = 0; k < HH; ++k) sum = fmaf(hr[k], w[k], sum);
        out[(row0 + m) * VOCAB + v] = sum;
    }
}

extern "C" void kernel_launch(void* const* d_in, const int* in_sizes, int n_in,
                              void* d_out, int out_size) {
    const void*  x    = d_in[0];
    const float* emb  = (const float*)d_in[1];
    const float* W_ih = (const float*)d_in[2];
    const float* W_hh = (const float*)d_in[3];
    const float* b_ih = (const float*)d_in[4];
    const float* b_hh = (const float*)d_in[5];
    const float* W_fc = (const float*)d_in[6];
    const float* b_fc = (const float*)d_in[7];
    float* out = (float*)d_out;

    static int smem_set = 0;
    if (!smem_set) {
        cudaFuncSetAttribute(gru_kernel,
                             cudaFuncAttributeMaxDynamicSharedMemorySize,
                             SMEM_BYTES);
        smem_set = 1;
    }

    detect_kernel<<<1, 1>>>((const int*)x);
    tok_kernel<<<(BB * TT + 255) / 256, 256>>>(x);
    gi_kernel<<<1, G3>>>(W_ih, emb, b_ih);
    gru_kernel<<<NBLK, NTHR, SMEM_BYTES>>>(W_hh, b_hh, W_fc, b_fc, out);
}

// round 6
// speedup vs baseline: 1.9186x; 1.0871x over previous
#include <cuda_runtime.h>

#define BB 2048
#define TT 512
#define VOCAB 4
#define EE 64
#define HH 128
#define G3 384        // 3*H
#define MTILE 16
#define NBLK (BB/MTILE)   // 128 CTAs
#define NTHR 256          // 128 units x 2 m-groups of 8 rows

// ---- scratch (no allocs allowed) ----
__device__ float         g_gi[VOCAB * G3];
__device__ unsigned char g_tok[TT * BB];
__device__ int           g_is64;

// ---- smem layout (bytes) ----
#define OFF_W    0                      // 384*128 f32 swizzled   = 196608
#define OFF_H0   196608                 // 16*128 f32 h buf 0     =   8192
#define OFF_H1   204800                 // 16*128 f32 h buf 1     =   8192
#define OFF_GI   212992                 // 4*384 f32              =   6144
#define OFF_TOK  219136                 // 2 groups x 2 bufs x 8  =     32
#define SMEM_BYTES 219168

// packed fp32x2 FMA (Blackwell)
__device__ __forceinline__ unsigned long long fma2(unsigned long long a,
                                                   unsigned long long b,
                                                   unsigned long long c) {
    unsigned long long d;
    asm("fma.rn.f32x2 %0, %1, %2, %3;" : "=l"(d) : "l"(a), "l"(b), "l"(c));
    return d;
}
__device__ __forceinline__ float reduce2(unsigned long long a) {
    unsigned int lo, hi;
    asm("mov.b64 {%0, %1}, %2;" : "=r"(lo), "=r"(hi) : "l"(a));
    return __uint_as_float(lo) + __uint_as_float(hi);
}
__device__ __forceinline__ float tanh_fast(float x) {
    float y;
    asm("tanh.approx.f32 %0, %1;" : "=f"(y) : "f"(x));
    return y;
}
__device__ __forceinline__ float sigmoid_fast(float x) {
    return fmaf(tanh_fast(0.5f * x), 0.5f, 0.5f);
}
// group barrier: 128 threads (4 aligned warps) of m-group mg
__device__ __forceinline__ void group_bar(int mg) {
    asm volatile("bar.sync %0, 128;" :: "r"(mg + 1) : "memory");
}

__global__ void detect_kernel(const int* __restrict__ x32) {
    int all_zero = 1;
    for (int i = 1; i < 128; i += 2) all_zero &= (x32[i] == 0);
    g_is64 = all_zero;
}

__global__ void tok_kernel(const void* __restrict__ xraw) {
    int i = blockIdx.x * blockDim.x + threadIdx.x;
    if (i >= BB * TT) return;
    int b = i / TT, t = i % TT;
    int v;
    if (g_is64) v = (int)((const long long*)xraw)[i];
    else        v = ((const int*)xraw)[i];
    g_tok[t * BB + b] = (unsigned char)v;
}

__global__ void gi_kernel(const float* __restrict__ W_ih,
                          const float* __restrict__ emb,
                          const float* __restrict__ b_ih) {
    int g = threadIdx.x;
    if (g >= G3) return;
    float bi = b_ih[g];
    for (int v = 0; v < VOCAB; ++v) {
        float s = bi;
#pragma unroll 8
        for (int e = 0; e < EE; ++e) s += W_ih[g * EE + e] * emb[v * EE + e];
        g_gi[v * G3 + g] = s;
    }
}

extern __shared__ char smem[];

__global__ __launch_bounds__(NTHR, 1)
void gru_kernel(const float* __restrict__ W_hh, const float* __restrict__ b_hh,
                const float* __restrict__ W_fc, const float* __restrict__ b_fc,
                float* __restrict__ out) {
    float*         h0_s  = (float*)(smem + OFF_H0);
    float*         h1_s  = (float*)(smem + OFF_H1);
    float*         gi_s  = (float*)(smem + OFF_GI);
    unsigned char* tok_s = (unsigned char*)(smem + OFF_TOK);

    const int tid  = threadIdx.x;     // 0..255
    const int j    = tid & 127;       // hidden unit
    const int mg   = tid >> 7;        // m-group: rows 8*mg..8*mg+7
    const int m0   = mg * 8;
    const int row0 = blockIdx.x * MTILE;

    // W_hh -> smem, XOR-swizzled on 16B granules (row r granule c at c^(r&7))
    {
        float4* W_s4 = (float4*)(smem + OFF_W);
        for (int r = tid; r < G3; r += NTHR) {
            const float4* Wg = (const float4*)(W_hh + r * HH);
            int swr = r & 7;
#pragma unroll 4
            for (int c = 0; c < 32; ++c) W_s4[r * 32 + (c ^ swr)] = Wg[c];
        }
    }
    for (int i = tid; i < VOCAB * G3; i += NTHR) gi_s[i] = g_gi[i];
    for (int i = tid; i < MTILE * HH; i += NTHR) h0_s[i] = 0.0f;
    // group-local token staging: lane j<8 of group mg owns row m0+j
    if (j < 8) tok_s[mg * 16 + 0 * 8 + j] = g_tok[0 * BB + row0 + m0 + j];

    const unsigned long long bR = (unsigned long long)__float_as_uint(b_hh[j]);
    const unsigned long long bZ = (unsigned long long)__float_as_uint(b_hh[128 + j]);
    const unsigned long long bN = (unsigned long long)__float_as_uint(b_hh[256 + j]);
    __syncthreads();

    const int sw = j & 7;   // (j+128)&7 == (j+256)&7 == j&7
    const ulonglong2* Wr = (const ulonglong2*)(smem + OFF_W) + (j)       * 32;
    const ulonglong2* Wz = (const ulonglong2*)(smem + OFF_W) + (128 + j) * 32;
    const ulonglong2* Wn = (const ulonglong2*)(smem + OFF_W) + (256 + j) * 32;

    for (int t = 0; t < TT; ++t) {
        const int cur = t & 1;
        float* h_cur = cur ? h1_s : h0_s;
        float* h_nxt = cur ? h0_s : h1_s;
        const ulonglong2* hc2 = (const ulonglong2*)h_cur;

        // prefetch old-h (epilogue operand) early: latency hidden by GEMM
        float ho[8];
#pragma unroll
        for (int m = 0; m < 8; ++m) ho[m] = h_cur[(m0 + m) * HH + j];

        // prefetch next step's tokens for this group's rows
        unsigned char nt = 0;
        if (j < 8 && t + 1 < TT) nt = g_tok[(t + 1) * BB + row0 + m0 + j];

        // ---- gh = b_hh + h @ W_hh^T for all 3 gates of unit j, 8 rows ----
        unsigned long long aR[8], aZ[8], aN[8];
#pragma unroll
        for (int m = 0; m < 8; ++m) { aR[m] = bR; aZ[m] = bZ; aN[m] = bN; }

        // depth-1 software pipeline on the W granules (branch-free wrap)
        ulonglong2 wr = Wr[sw], wz = Wz[sw], wn = Wn[sw];
#pragma unroll 4
        for (int c = 0; c < 32; ++c) {
            const int cn = ((c + 1) & 31) ^ sw;
            ulonglong2 wr_n = Wr[cn];
            ulonglong2 wz_n = Wz[cn];
            ulonglong2 wn_n = Wn[cn];
#pragma unroll
            for (int m = 0; m < 8; ++m) {
                ulonglong2 hv = hc2[(m0 + m) * 32 + c];   // warp-broadcast
                aR[m] = fma2(hv.x, wr.x, aR[m]);
                aR[m] = fma2(hv.y, wr.y, aR[m]);
                aZ[m] = fma2(hv.x, wz.x, aZ[m]);
                aZ[m] = fma2(hv.y, wz.y, aZ[m]);
                aN[m] = fma2(hv.x, wn.x, aN[m]);
                aN[m] = fma2(hv.y, wn.y, aN[m]);
            }
            wr = wr_n; wz = wz_n; wn = wn_n;
        }

        // ---- gates + h update, all thread-local ----
        float sR[8], sZ[8], sN[8];
#pragma unroll
        for (int m = 0; m < 8; ++m) {
            sR[m] = reduce2(aR[m]);
            sZ[m] = reduce2(aZ[m]);
            sN[m] = reduce2(aN[m]);
        }
#pragma unroll
        for (int m = 0; m < 8; ++m) {
            int   v  = tok_s[mg * 16 + cur * 8 + m];
            const float* gv = gi_s + v * G3;
            float r  = sigmoid_fast(gv[j]       + sR[m]);
            float z  = sigmoid_fast(gv[128 + j] + sZ[m]);
            float n  = tanh_fast   (gv[256 + j] + r * sN[m]);
            h_nxt[(m0 + m) * HH + j] = fmaf(z, ho[m] - n, n);  // (1-z)n + z*ho
        }
        if (j < 8) tok_s[mg * 16 + (cur ^ 1) * 8 + j] = nt;
        group_bar(mg);
    }

    __syncthreads();   // join groups: logits read all 16 rows

    // ---- logits = hT @ W_fc.T + b_fc  (final h in buffer 0: TT even) ----
    if (tid < MTILE * VOCAB) {
        int m = tid >> 2, v = tid & 3;
        float        sum = b_fc[v];
        const float* w   = W_fc + v * HH;
        const float* hr  = h0_s + m * HH;
#pragma unroll 8
        for (int k = 0; k < HH; ++k) sum = fmaf(hr[k], w[k], sum);
        out[(row0 + m) * VOCAB + v] = sum;
    }
}

extern "C" void kernel_launch(void* const* d_in, const int* in_sizes, int n_in,
                              void* d_out, int out_size) {
    const void*  x    = d_in[0];
    const float* emb  = (const float*)d_in[1];
    const float* W_ih = (const float*)d_in[2];
    const float* W_hh = (const float*)d_in[3];
    const float* b_ih = (const float*)d_in[4];
    const float* b_hh = (const float*)d_in[5];
    const float* W_fc = (const float*)d_in[6];
    const float* b_fc = (const float*)d_in[7];
    float* out = (float*)d_out;

    static int smem_set = 0;
    if (!smem_set) {
        cudaFuncSetAttribute(gru_kernel,
                             cudaFuncAttributeMaxDynamicSharedMemorySize,
                             SMEM_BYTES);
        smem_set = 1;
    }

    detect_kernel<<<1, 1>>>((const int*)x);
    tok_kernel<<<(BB * TT + 255) / 256, 256>>>(x);
    gi_kernel<<<1, G3>>>(W_ih, emb, b_ih);
    gru_kernel<<<NBLK, NTHR, SMEM_BYTES>>>(W_hh, b_hh, W_fc, b_fc, out);
}